// round 5
// baseline (speedup 1.0000x reference)
#include <cuda_runtime.h>
#include <cstdint>

// Problem constants (fixed by setup_inputs)
#define N_SRC  100000
#define N_DST  20000
#define NE     600000
#define D      128
#define KDIM   256          // 2*D
#define OUT_F  128

// GEMM tile config
#define BM     64
#define WPAD   132
#define SMEM_BYTES ((BM * KDIM + KDIM * WPAD) * 4)   // 200704 B

// Scratch (allocation-free rule: __device__ globals)
__device__ int   g_count[N_DST];
__device__ int   g_off[N_DST];
__device__ int   g_cur[N_DST];
__device__ int   g_src_sorted[NE];
__device__ __align__(16) float g_nb[N_DST * D];   // averaged neighbor features

// ---------------------------------------------------------------------------
// 1: zero degree counts
// ---------------------------------------------------------------------------
__global__ void zero_kernel() {
    int i = blockIdx.x * blockDim.x + threadIdx.x;
    if (i < N_DST) g_count[i] = 0;
}

// ---------------------------------------------------------------------------
// 2: count degree per dst  (edge indices are INT32 — JAX x64 is disabled)
// ---------------------------------------------------------------------------
__global__ void count_kernel(const int* __restrict__ edst) {
    int i = blockIdx.x * blockDim.x + threadIdx.x;
    if (i < NE) atomicAdd(&g_count[edst[i]], 1);
}

// ---------------------------------------------------------------------------
// 3: exclusive scan of counts -> offsets (+cursor copy). Single block, 1024 thr.
// ---------------------------------------------------------------------------
__global__ void __launch_bounds__(1024, 1) scan_kernel() {
    __shared__ int s[1024];
    __shared__ int carry;
    const int tid = threadIdx.x;
    if (tid == 0) carry = 0;
    __syncthreads();

    for (int base = 0; base < N_DST; base += 1024) {
        int i = base + tid;
        int v = (i < N_DST) ? g_count[i] : 0;
        s[tid] = v;
        __syncthreads();
        for (int d = 1; d < 1024; d <<= 1) {
            int t = (tid >= d) ? s[tid - d] : 0;
            __syncthreads();
            s[tid] += t;
            __syncthreads();
        }
        if (i < N_DST) {
            int excl = carry + s[tid] - v;
            g_off[i] = excl;
            g_cur[i] = excl;
        }
        __syncthreads();
        if (tid == 0) carry += s[1023];
        __syncthreads();
    }
}

// ---------------------------------------------------------------------------
// 4: bucket-fill src indices into CSR order
// ---------------------------------------------------------------------------
__global__ void fill_kernel(const int* __restrict__ esrc,
                            const int* __restrict__ edst) {
    int i = blockIdx.x * blockDim.x + threadIdx.x;
    if (i < NE) {
        int dst = edst[i];
        int pos = atomicAdd(&g_cur[dst], 1);
        g_src_sorted[pos] = esrc[i];
    }
}

// ---------------------------------------------------------------------------
// 5: atomic-free aggregation. One warp per dst row.
// Lane l accumulates float4 at column 4l across the row's edges.
// ---------------------------------------------------------------------------
__global__ void agg_kernel(const float4* __restrict__ h4) {
    int row  = (blockIdx.x * blockDim.x + threadIdx.x) >> 5;
    int lane = threadIdx.x & 31;
    if (row >= N_DST) return;

    int start = g_off[row];
    int cnt   = g_count[row];

    float4 acc = make_float4(0.f, 0.f, 0.f, 0.f);
    int s_next = (cnt > 0) ? g_src_sorted[start] : 0;   // broadcast load
    for (int j = 0; j < cnt; j++) {
        int s = s_next;
        if (j + 1 < cnt) s_next = g_src_sorted[start + j + 1];  // prefetch index
        float4 v = h4[s * (D / 4) + lane];   // coalesced 512B row read, L2-resident
        acc.x += v.x; acc.y += v.y; acc.z += v.z; acc.w += v.w;
    }
    float inv = 1.0f / fmaxf((float)cnt, 1.0f);
    acc.x *= inv; acc.y *= inv; acc.z *= inv; acc.w *= inv;
    ((float4*)g_nb)[row * (D / 4) + lane] = acc;
}

// ---------------------------------------------------------------------------
// 6: out = relu( [h[:N_DST] | h_neigh] @ W^T + b )
// 256 threads, BM=64 rows x 128 cols; thread tile 8x4.
// ---------------------------------------------------------------------------
__global__ void __launch_bounds__(256, 1)
gemm_kernel(const float* __restrict__ h,
            const float* __restrict__ W,     // [OUT_F, KDIM] row-major
            const float* __restrict__ bias,
            float* __restrict__ out) {
    extern __shared__ float smem[];
    float* zs = smem;                 // [BM][KDIM]
    float* ws = smem + BM * KDIM;     // [KDIM][WPAD]  (W transposed, k-major)

    const int t  = threadIdx.x;
    const int r0 = blockIdx.x * BM;

    // Load + transpose W into smem: ws[k][o] = W[o][k]
    for (int i = t; i < OUT_F * KDIM; i += 256) {
        int o = i >> 8;        // / KDIM
        int k = i & 255;       // % KDIM
        ws[k * WPAD + o] = W[i];
    }

    // Build z tile: cols [0,128) = h_dst, cols [128,256) = averaged neighbors
    for (int i = t; i < BM * KDIM; i += 256) {
        int r  = i >> 8;
        int k  = i & 255;
        int rg = r0 + r;
        int rc = rg < N_DST ? rg : (N_DST - 1);   // clamp for partial last block
        float v = (k < D) ? h[rc * D + k] : g_nb[rc * D + (k - D)];
        zs[r * KDIM + k] = v;
    }
    __syncthreads();

    const int lane = t & 31;     // out-col group
    const int wrp  = t >> 5;     // row group (constant within warp -> z loads broadcast)

    float acc[8][4];
#pragma unroll
    for (int i = 0; i < 8; i++)
#pragma unroll
        for (int j = 0; j < 4; j++) acc[i][j] = 0.0f;

    const float* zrow = zs + (wrp * 8) * KDIM;

    for (int k = 0; k < KDIM; k += 4) {
        float4 wv0 = *(const float4*)&ws[(k + 0) * WPAD + lane * 4];
        float4 wv1 = *(const float4*)&ws[(k + 1) * WPAD + lane * 4];
        float4 wv2 = *(const float4*)&ws[(k + 2) * WPAD + lane * 4];
        float4 wv3 = *(const float4*)&ws[(k + 3) * WPAD + lane * 4];
#pragma unroll
        for (int i = 0; i < 8; i++) {
            float4 z4 = *(const float4*)&zrow[i * KDIM + k];   // broadcast within warp
            acc[i][0] = fmaf(z4.x, wv0.x, acc[i][0]);
            acc[i][1] = fmaf(z4.x, wv0.y, acc[i][1]);
            acc[i][2] = fmaf(z4.x, wv0.z, acc[i][2]);
            acc[i][3] = fmaf(z4.x, wv0.w, acc[i][3]);
            acc[i][0] = fmaf(z4.y, wv1.x, acc[i][0]);
            acc[i][1] = fmaf(z4.y, wv1.y, acc[i][1]);
            acc[i][2] = fmaf(z4.y, wv1.z, acc[i][2]);
            acc[i][3] = fmaf(z4.y, wv1.w, acc[i][3]);
            acc[i][0] = fmaf(z4.z, wv2.x, acc[i][0]);
            acc[i][1] = fmaf(z4.z, wv2.y, acc[i][1]);
            acc[i][2] = fmaf(z4.z, wv2.z, acc[i][2]);
            acc[i][3] = fmaf(z4.z, wv2.w, acc[i][3]);
            acc[i][0] = fmaf(z4.w, wv3.x, acc[i][0]);
            acc[i][1] = fmaf(z4.w, wv3.y, acc[i][1]);
            acc[i][2] = fmaf(z4.w, wv3.z, acc[i][2]);
            acc[i][3] = fmaf(z4.w, wv3.w, acc[i][3]);
        }
    }

    float4 bv = *(const float4*)&bias[lane * 4];

#pragma unroll
    for (int i = 0; i < 8; i++) {
        int rg = r0 + wrp * 8 + i;
        if (rg < N_DST) {
            float4 res;
            res.x = fmaxf(acc[i][0] + bv.x, 0.0f);
            res.y = fmaxf(acc[i][1] + bv.y, 0.0f);
            res.z = fmaxf(acc[i][2] + bv.z, 0.0f);
            res.w = fmaxf(acc[i][3] + bv.w, 0.0f);
            *(float4*)&out[rg * OUT_F + lane * 4] = res;
        }
    }
}

// ---------------------------------------------------------------------------
extern "C" void kernel_launch(void* const* d_in, const int* in_sizes, int n_in,
                              void* d_out, int out_size) {
    const float* h    = (const float*)d_in[0];
    const int*   esrc = (const int*)d_in[1];    // int32: JAX x64 disabled
    const int*   edst = (const int*)d_in[2];    // int32
    const float* W    = (const float*)d_in[3];
    const float* bias = (const float*)d_in[4];
    float*       out  = (float*)d_out;

    cudaFuncSetAttribute(gemm_kernel,
                         cudaFuncAttributeMaxDynamicSharedMemorySize, SMEM_BYTES);

    zero_kernel<<<(N_DST + 255) / 256, 256>>>();
    count_kernel<<<(NE + 255) / 256, 256>>>(edst);
    scan_kernel<<<1, 1024>>>();
    fill_kernel<<<(NE + 255) / 256, 256>>>(esrc, edst);
    agg_kernel<<<(N_DST * 32 + 255) / 256, 256>>>((const float4*)h);
    gemm_kernel<<<(N_DST + BM - 1) / BM, 256, SMEM_BYTES>>>(h, W, bias, out);
}

// round 6
// speedup vs baseline: 1.2091x; 1.2091x over previous
#include <cuda_runtime.h>
#include <cstdint>

typedef unsigned long long ull;

// Problem constants (fixed by setup_inputs)
#define N_SRC  100000
#define N_DST  20000
#define NE     600000
#define D      128
#define KDIM   256          // 2*D
#define OUT_F  128

// GEMM tile config
#define BM     48           // 417 blocks -> better wave balance than 64
#define ROWS_W 6            // rows per warp (3 row-pairs)
#define WPAD   132
#define ZPAD   50           // BM + 2
#define SMEM_BYTES ((KDIM * ZPAD + KDIM * WPAD) * 4)   // 51200 + 135168 = 186368 B

// Scratch (allocation-free rule: __device__ globals)
__device__ int   g_count[N_DST];
__device__ int   g_off[N_DST];
__device__ int   g_cur[N_DST];
__device__ int   g_src_sorted[NE];
__device__ __align__(16) float g_nb[N_DST * D];   // averaged neighbor features

// ---- packed f32x2 helpers (Blackwell FFMA2) --------------------------------
__device__ __forceinline__ ull pack2(float a, float b) {
    ull r; asm("mov.b64 %0, {%1, %2};" : "=l"(r) : "f"(a), "f"(b)); return r;
}
__device__ __forceinline__ void unpack2(ull v, float& lo, float& hi) {
    asm("mov.b64 {%0, %1}, %2;" : "=f"(lo), "=f"(hi) : "l"(v));
}
__device__ __forceinline__ ull fma2(ull a, ull b, ull c) {
    ull d; asm("fma.rn.f32x2 %0, %1, %2, %3;" : "=l"(d) : "l"(a), "l"(b), "l"(c));
    return d;
}

// ---------------------------------------------------------------------------
// 1: zero degree counts
// ---------------------------------------------------------------------------
__global__ void zero_kernel() {
    int i = blockIdx.x * blockDim.x + threadIdx.x;
    if (i < N_DST) g_count[i] = 0;
}

// ---------------------------------------------------------------------------
// 2: count degree per dst (edge indices are INT32)
// ---------------------------------------------------------------------------
__global__ void count_kernel(const int* __restrict__ edst) {
    int i = blockIdx.x * blockDim.x + threadIdx.x;
    if (i < NE) atomicAdd(&g_count[edst[i]], 1);
}

// ---------------------------------------------------------------------------
// 3: exclusive scan of counts -> offsets. Single block, shuffle-based.
// Thread t serially scans elements [t*20, t*20+20). ~2 barriers total.
// ---------------------------------------------------------------------------
#define PER_T 20
__global__ void __launch_bounds__(1024, 1) scan_kernel() {
    __shared__ int warp_sums[32];
    const int tid  = threadIdx.x;
    const int lane = tid & 31;
    const int wrp  = tid >> 5;

    int vals[PER_T];
    int base = tid * PER_T;
    int total = 0;
#pragma unroll
    for (int j = 0; j < PER_T; j++) {
        int idx = base + j;
        int v = (idx < N_DST) ? g_count[idx] : 0;
        vals[j] = total;       // local exclusive prefix
        total += v;
    }

    // warp inclusive scan of totals
    int inc = total;
#pragma unroll
    for (int d = 1; d < 32; d <<= 1) {
        int t = __shfl_up_sync(0xffffffffu, inc, d);
        if (lane >= d) inc += t;
    }
    if (lane == 31) warp_sums[wrp] = inc;
    __syncthreads();

    if (wrp == 0) {
        int w = warp_sums[lane];
        int winc = w;
#pragma unroll
        for (int d = 1; d < 32; d <<= 1) {
            int t = __shfl_up_sync(0xffffffffu, winc, d);
            if (lane >= d) winc += t;
        }
        warp_sums[lane] = winc - w;   // exclusive warp base
    }
    __syncthreads();

    int thread_base = warp_sums[wrp] + (inc - total);   // exclusive across threads
#pragma unroll
    for (int j = 0; j < PER_T; j++) {
        int idx = base + j;
        if (idx < N_DST) {
            int off = thread_base + vals[j];
            g_off[idx] = off;
            g_cur[idx] = off;
        }
    }
}

// ---------------------------------------------------------------------------
// 4: bucket-fill src indices into CSR order
// ---------------------------------------------------------------------------
__global__ void fill_kernel(const int* __restrict__ esrc,
                            const int* __restrict__ edst) {
    int i = blockIdx.x * blockDim.x + threadIdx.x;
    if (i < NE) {
        int dst = edst[i];
        int pos = atomicAdd(&g_cur[dst], 1);
        g_src_sorted[pos] = esrc[i];
    }
}

// ---------------------------------------------------------------------------
// 5: atomic-free aggregation. One warp per dst row, 4-way unrolled (MLP=4).
// ---------------------------------------------------------------------------
__global__ void agg_kernel(const float4* __restrict__ h4) {
    int row  = (blockIdx.x * blockDim.x + threadIdx.x) >> 5;
    int lane = threadIdx.x & 31;
    if (row >= N_DST) return;

    int start = g_off[row];
    int cnt   = g_count[row];

    float4 a0 = make_float4(0.f, 0.f, 0.f, 0.f);
    float4 a1 = make_float4(0.f, 0.f, 0.f, 0.f);

    int j = 0;
    for (; j + 4 <= cnt; j += 4) {
        int s0 = g_src_sorted[start + j + 0];
        int s1 = g_src_sorted[start + j + 1];
        int s2 = g_src_sorted[start + j + 2];
        int s3 = g_src_sorted[start + j + 3];
        float4 v0 = h4[s0 * (D / 4) + lane];
        float4 v1 = h4[s1 * (D / 4) + lane];
        float4 v2 = h4[s2 * (D / 4) + lane];
        float4 v3 = h4[s3 * (D / 4) + lane];
        a0.x += v0.x + v1.x; a0.y += v0.y + v1.y;
        a0.z += v0.z + v1.z; a0.w += v0.w + v1.w;
        a1.x += v2.x + v3.x; a1.y += v2.y + v3.y;
        a1.z += v2.z + v3.z; a1.w += v2.w + v3.w;
    }
    for (; j < cnt; j++) {
        int s = g_src_sorted[start + j];
        float4 v = h4[s * (D / 4) + lane];
        a0.x += v.x; a0.y += v.y; a0.z += v.z; a0.w += v.w;
    }
    float inv = 1.0f / fmaxf((float)cnt, 1.0f);
    float4 acc;
    acc.x = (a0.x + a1.x) * inv;
    acc.y = (a0.y + a1.y) * inv;
    acc.z = (a0.z + a1.z) * inv;
    acc.w = (a0.w + a1.w) * inv;
    ((float4*)g_nb)[row * (D / 4) + lane] = acc;
}

// ---------------------------------------------------------------------------
// 6: out = relu( [h[:N_DST] | h_neigh] @ W^T + b )  via packed FFMA2
// 256 threads. Warp w: rows [6w, 6w+6) (3 pairs). Lane: cols [4l, 4l+4).
// z tile stored TRANSPOSED: zsT[k][r] so a row-pair is one LDS.64.
// ---------------------------------------------------------------------------
__global__ void __launch_bounds__(256, 1)
gemm_kernel(const float* __restrict__ h,
            const float* __restrict__ W,     // [OUT_F, KDIM] row-major
            const float* __restrict__ bias,
            float* __restrict__ out) {
    extern __shared__ float smem[];
    float* zsT = smem;                  // [KDIM][ZPAD]
    float* ws  = smem + KDIM * ZPAD;    // [KDIM][WPAD]  (W transposed, k-major)

    const int t  = threadIdx.x;
    const int r0 = blockIdx.x * BM;

    // Load + transpose W into smem: ws[k][o] = W[o][k]
    for (int i = t; i < OUT_F * KDIM; i += 256) {
        int o = i >> 8;        // / KDIM
        int k = i & 255;       // % KDIM
        ws[k * WPAD + o] = W[i];
    }

    // Build transposed z tile: zsT[k][r]; k<128 -> h_dst, k>=128 -> h_neigh
    for (int i = t; i < BM * KDIM; i += 256) {
        int r  = i >> 8;
        int k  = i & 255;
        int rg = r0 + r;
        int rc = rg < N_DST ? rg : (N_DST - 1);   // clamp for partial last block
        float v = (k < D) ? h[rc * D + k] : g_nb[rc * D + (k - D)];
        zsT[k * ZPAD + r] = v;
    }
    __syncthreads();

    const int lane = t & 31;
    const int wrp  = t >> 5;

    ull acc[3][4];
#pragma unroll
    for (int p = 0; p < 3; p++)
#pragma unroll
        for (int jj = 0; jj < 4; jj++) acc[p][jj] = 0ULL;

    const float* zcol = zsT + wrp * ROWS_W;
    const float* wrow = ws + lane * 4;

#pragma unroll 8
    for (int k = 0; k < KDIM; k++) {
        float4 w4 = *(const float4*)&wrow[k * WPAD];
        ull w0 = pack2(w4.x, w4.x);
        ull w1 = pack2(w4.y, w4.y);
        ull w2 = pack2(w4.z, w4.z);
        ull w3 = pack2(w4.w, w4.w);
        const float* z = zcol + k * ZPAD;
        ull z0 = *(const ull*)&z[0];    // rows (6w, 6w+1)   — broadcast in warp
        ull z1 = *(const ull*)&z[2];    // rows (6w+2, 6w+3)
        ull z2 = *(const ull*)&z[4];    // rows (6w+4, 6w+5)
        acc[0][0] = fma2(z0, w0, acc[0][0]);
        acc[0][1] = fma2(z0, w1, acc[0][1]);
        acc[0][2] = fma2(z0, w2, acc[0][2]);
        acc[0][3] = fma2(z0, w3, acc[0][3]);
        acc[1][0] = fma2(z1, w0, acc[1][0]);
        acc[1][1] = fma2(z1, w1, acc[1][1]);
        acc[1][2] = fma2(z1, w2, acc[1][2]);
        acc[1][3] = fma2(z1, w3, acc[1][3]);
        acc[2][0] = fma2(z2, w0, acc[2][0]);
        acc[2][1] = fma2(z2, w1, acc[2][1]);
        acc[2][2] = fma2(z2, w2, acc[2][2]);
        acc[2][3] = fma2(z2, w3, acc[2][3]);
    }

    float4 bv = *(const float4*)&bias[lane * 4];

#pragma unroll
    for (int p = 0; p < 3; p++) {
        float lo0, hi0, lo1, hi1, lo2, hi2, lo3, hi3;
        unpack2(acc[p][0], lo0, hi0);
        unpack2(acc[p][1], lo1, hi1);
        unpack2(acc[p][2], lo2, hi2);
        unpack2(acc[p][3], lo3, hi3);
        int rg = r0 + wrp * ROWS_W + 2 * p;
        if (rg < N_DST) {
            float4 res;
            res.x = fmaxf(lo0 + bv.x, 0.0f);
            res.y = fmaxf(lo1 + bv.y, 0.0f);
            res.z = fmaxf(lo2 + bv.z, 0.0f);
            res.w = fmaxf(lo3 + bv.w, 0.0f);
            *(float4*)&out[rg * OUT_F + lane * 4] = res;
        }
        if (rg + 1 < N_DST) {
            float4 res;
            res.x = fmaxf(hi0 + bv.x, 0.0f);
            res.y = fmaxf(hi1 + bv.y, 0.0f);
            res.z = fmaxf(hi2 + bv.z, 0.0f);
            res.w = fmaxf(hi3 + bv.w, 0.0f);
            *(float4*)&out[(rg + 1) * OUT_F + lane * 4] = res;
        }
    }
}

// ---------------------------------------------------------------------------
extern "C" void kernel_launch(void* const* d_in, const int* in_sizes, int n_in,
                              void* d_out, int out_size) {
    const float* h    = (const float*)d_in[0];
    const int*   esrc = (const int*)d_in[1];    // int32: JAX x64 disabled
    const int*   edst = (const int*)d_in[2];    // int32
    const float* W    = (const float*)d_in[3];
    const float* bias = (const float*)d_in[4];
    float*       out  = (float*)d_out;

    cudaFuncSetAttribute(gemm_kernel,
                         cudaFuncAttributeMaxDynamicSharedMemorySize, SMEM_BYTES);

    zero_kernel<<<(N_DST + 255) / 256, 256>>>();
    count_kernel<<<(NE + 255) / 256, 256>>>(edst);
    scan_kernel<<<1, 1024>>>();
    fill_kernel<<<(NE + 255) / 256, 256>>>(esrc, edst);
    agg_kernel<<<(N_DST * 32 + 255) / 256, 256>>>((const float4*)h);
    gemm_kernel<<<(N_DST + BM - 1) / BM, 256, SMEM_BYTES>>>(h, W, bias, out);
}

// round 7
// speedup vs baseline: 1.3466x; 1.1137x over previous
#include <cuda_runtime.h>
#include <cstdint>

typedef unsigned long long ull;

// Problem constants (fixed by setup_inputs)
#define N_SRC  100000
#define N_DST  20000
#define NE     600000
#define D      128
#define KDIM   256          // 2*D
#define OUT_F  128

// GEMM tile config
#define BM     48
#define ROWS_W 6            // rows per warp (3 row-pairs)
#define WPAD   128          // no transpose in-block anymore -> no pad needed
#define ZPAD   50           // BM + 2
#define SMEM_BYTES ((KDIM * ZPAD + KDIM * WPAD) * 4)   // 51200 + 131072 = 182272 B

// Scratch (allocation-free rule: __device__ globals)
__device__ int   g_count[N_DST];
__device__ int   g_off[N_DST];
__device__ int   g_cur[N_DST];
__device__ int   g_src_sorted[NE];
__device__ __align__(16) float g_nb[N_DST * D];     // averaged neighbor features
__device__ __align__(16) float g_Wt[KDIM * OUT_F];  // W transposed: g_Wt[k][o]

// ---- packed f32x2 helpers (Blackwell FFMA2) --------------------------------
__device__ __forceinline__ ull pack2(float a, float b) {
    ull r; asm("mov.b64 %0, {%1, %2};" : "=l"(r) : "f"(a), "f"(b)); return r;
}
__device__ __forceinline__ void unpack2(ull v, float& lo, float& hi) {
    asm("mov.b64 {%0, %1}, %2;" : "=f"(lo), "=f"(hi) : "l"(v));
}
__device__ __forceinline__ ull fma2(ull a, ull b, ull c) {
    ull d; asm("fma.rn.f32x2 %0, %1, %2, %3;" : "=l"(d) : "l"(a), "l"(b), "l"(c));
    return d;
}

// ---------------------------------------------------------------------------
// 1: transpose W once: g_Wt[k*128+o] = W[o*256+k]
// ---------------------------------------------------------------------------
__global__ void wt_kernel(const float* __restrict__ W) {
    int i = blockIdx.x * blockDim.x + threadIdx.x;   // 32768 elems
    if (i < OUT_F * KDIM) {
        int o = i >> 8;
        int k = i & 255;
        g_Wt[k * OUT_F + o] = W[i];
    }
}

// ---------------------------------------------------------------------------
// 2: count degree per dst — 4 edges/thread (int4), independent atomics
// ---------------------------------------------------------------------------
__global__ void count_kernel(const int4* __restrict__ edst4) {
    int i = blockIdx.x * blockDim.x + threadIdx.x;
    if (i < NE / 4) {
        int4 d = edst4[i];
        atomicAdd(&g_count[d.x], 1);
        atomicAdd(&g_count[d.y], 1);
        atomicAdd(&g_count[d.z], 1);
        atomicAdd(&g_count[d.w], 1);
    }
}

// ---------------------------------------------------------------------------
// 3: exclusive scan of counts -> offsets. Single block, shuffle-based.
// ---------------------------------------------------------------------------
#define PER_T 20
__global__ void __launch_bounds__(1024, 1) scan_kernel() {
    __shared__ int warp_sums[32];
    const int tid  = threadIdx.x;
    const int lane = tid & 31;
    const int wrp  = tid >> 5;

    int vals[PER_T];
    int base = tid * PER_T;
    int total = 0;
#pragma unroll
    for (int j = 0; j < PER_T; j++) {
        int idx = base + j;
        int v = (idx < N_DST) ? g_count[idx] : 0;
        vals[j] = total;
        total += v;
    }

    int inc = total;
#pragma unroll
    for (int d = 1; d < 32; d <<= 1) {
        int t = __shfl_up_sync(0xffffffffu, inc, d);
        if (lane >= d) inc += t;
    }
    if (lane == 31) warp_sums[wrp] = inc;
    __syncthreads();

    if (wrp == 0) {
        int w = warp_sums[lane];
        int winc = w;
#pragma unroll
        for (int d = 1; d < 32; d <<= 1) {
            int t = __shfl_up_sync(0xffffffffu, winc, d);
            if (lane >= d) winc += t;
        }
        warp_sums[lane] = winc - w;
    }
    __syncthreads();

    int thread_base = warp_sums[wrp] + (inc - total);
#pragma unroll
    for (int j = 0; j < PER_T; j++) {
        int idx = base + j;
        if (idx < N_DST) {
            int off = thread_base + vals[j];
            g_off[idx] = off;
            g_cur[idx] = off;
        }
    }
}

// ---------------------------------------------------------------------------
// 4: bucket-fill src indices into CSR order — 4 edges/thread (MLP=4)
// ---------------------------------------------------------------------------
__global__ void fill_kernel(const int4* __restrict__ esrc4,
                            const int4* __restrict__ edst4) {
    int i = blockIdx.x * blockDim.x + threadIdx.x;
    if (i < NE / 4) {
        int4 d = edst4[i];
        int4 s = esrc4[i];
        int p0 = atomicAdd(&g_cur[d.x], 1);
        int p1 = atomicAdd(&g_cur[d.y], 1);
        int p2 = atomicAdd(&g_cur[d.z], 1);
        int p3 = atomicAdd(&g_cur[d.w], 1);
        g_src_sorted[p0] = s.x;
        g_src_sorted[p1] = s.y;
        g_src_sorted[p2] = s.z;
        g_src_sorted[p3] = s.w;
    }
}

// ---------------------------------------------------------------------------
// 5: atomic-free aggregation. One warp per dst row, 8-way unrolled (MLP=8).
// ---------------------------------------------------------------------------
__global__ void agg_kernel(const float4* __restrict__ h4) {
    int row  = (blockIdx.x * blockDim.x + threadIdx.x) >> 5;
    int lane = threadIdx.x & 31;
    if (row >= N_DST) return;

    int start = g_off[row];
    int cnt   = g_count[row];

    float4 a0 = make_float4(0.f, 0.f, 0.f, 0.f);
    float4 a1 = make_float4(0.f, 0.f, 0.f, 0.f);

    int j = 0;
    for (; j + 8 <= cnt; j += 8) {
        int s0 = g_src_sorted[start + j + 0];
        int s1 = g_src_sorted[start + j + 1];
        int s2 = g_src_sorted[start + j + 2];
        int s3 = g_src_sorted[start + j + 3];
        int s4 = g_src_sorted[start + j + 4];
        int s5 = g_src_sorted[start + j + 5];
        int s6 = g_src_sorted[start + j + 6];
        int s7 = g_src_sorted[start + j + 7];
        float4 v0 = h4[s0 * (D / 4) + lane];
        float4 v1 = h4[s1 * (D / 4) + lane];
        float4 v2 = h4[s2 * (D / 4) + lane];
        float4 v3 = h4[s3 * (D / 4) + lane];
        float4 v4 = h4[s4 * (D / 4) + lane];
        float4 v5 = h4[s5 * (D / 4) + lane];
        float4 v6 = h4[s6 * (D / 4) + lane];
        float4 v7 = h4[s7 * (D / 4) + lane];
        a0.x += (v0.x + v1.x) + (v2.x + v3.x);
        a0.y += (v0.y + v1.y) + (v2.y + v3.y);
        a0.z += (v0.z + v1.z) + (v2.z + v3.z);
        a0.w += (v0.w + v1.w) + (v2.w + v3.w);
        a1.x += (v4.x + v5.x) + (v6.x + v7.x);
        a1.y += (v4.y + v5.y) + (v6.y + v7.y);
        a1.z += (v4.z + v5.z) + (v6.z + v7.z);
        a1.w += (v4.w + v5.w) + (v6.w + v7.w);
    }
    for (; j < cnt; j++) {
        int s = g_src_sorted[start + j];
        float4 v = h4[s * (D / 4) + lane];
        a0.x += v.x; a0.y += v.y; a0.z += v.z; a0.w += v.w;
    }
    float inv = 1.0f / fmaxf((float)cnt, 1.0f);
    float4 acc;
    acc.x = (a0.x + a1.x) * inv;
    acc.y = (a0.y + a1.y) * inv;
    acc.z = (a0.z + a1.z) * inv;
    acc.w = (a0.w + a1.w) * inv;
    ((float4*)g_nb)[row * (D / 4) + lane] = acc;
}

// ---------------------------------------------------------------------------
// 6: out = relu( [h[:N_DST] | h_neigh] @ W^T + b )  via packed FFMA2
// ---------------------------------------------------------------------------
__global__ void __launch_bounds__(256, 1)
gemm_kernel(const float* __restrict__ h,
            const float* __restrict__ bias,
            float* __restrict__ out) {
    extern __shared__ float smem[];
    float* zsT = smem;                  // [KDIM][ZPAD]   (transposed z tile)
    float* ws  = smem + KDIM * ZPAD;    // [KDIM][WPAD]   (W^T, direct copy)

    const int t  = threadIdx.x;
    const int r0 = blockIdx.x * BM;

    // Copy W^T straight from g_Wt: float4, coalesced, conflict-free
    {
        const float4* src = (const float4*)g_Wt;
        float4*       dst = (float4*)ws;
        for (int i = t; i < KDIM * OUT_F / 4; i += 256) dst[i] = src[i];
    }

    // Build transposed z tile with float4 loads
    for (int i = t; i < BM * (KDIM / 4); i += 256) {
        int r  = i >> 6;          // / 64
        int k4 = i & 63;
        int rg = r0 + r;
        int rc = rg < N_DST ? rg : (N_DST - 1);
        float4 v = (k4 < 32) ? ((const float4*)h)[rc * 32 + k4]
                             : ((const float4*)g_nb)[rc * 32 + (k4 - 32)];
        int k = k4 * 4;
        zsT[(k + 0) * ZPAD + r] = v.x;
        zsT[(k + 1) * ZPAD + r] = v.y;
        zsT[(k + 2) * ZPAD + r] = v.z;
        zsT[(k + 3) * ZPAD + r] = v.w;
    }
    __syncthreads();

    const int lane = t & 31;
    const int wrp  = t >> 5;

    ull acc[3][4];
#pragma unroll
    for (int p = 0; p < 3; p++)
#pragma unroll
        for (int jj = 0; jj < 4; jj++) acc[p][jj] = 0ULL;

    const float* zcol = zsT + wrp * ROWS_W;
    const float* wrow = ws + lane * 4;

#pragma unroll 8
    for (int k = 0; k < KDIM; k++) {
        float4 w4 = *(const float4*)&wrow[k * WPAD];
        ull w0 = pack2(w4.x, w4.x);
        ull w1 = pack2(w4.y, w4.y);
        ull w2 = pack2(w4.z, w4.z);
        ull w3 = pack2(w4.w, w4.w);
        const float* z = zcol + k * ZPAD;
        ull z0 = *(const ull*)&z[0];
        ull z1 = *(const ull*)&z[2];
        ull z2 = *(const ull*)&z[4];
        acc[0][0] = fma2(z0, w0, acc[0][0]);
        acc[0][1] = fma2(z0, w1, acc[0][1]);
        acc[0][2] = fma2(z0, w2, acc[0][2]);
        acc[0][3] = fma2(z0, w3, acc[0][3]);
        acc[1][0] = fma2(z1, w0, acc[1][0]);
        acc[1][1] = fma2(z1, w1, acc[1][1]);
        acc[1][2] = fma2(z1, w2, acc[1][2]);
        acc[1][3] = fma2(z1, w3, acc[1][3]);
        acc[2][0] = fma2(z2, w0, acc[2][0]);
        acc[2][1] = fma2(z2, w1, acc[2][1]);
        acc[2][2] = fma2(z2, w2, acc[2][2]);
        acc[2][3] = fma2(z2, w3, acc[2][3]);
    }

    float4 bv = *(const float4*)&bias[lane * 4];

#pragma unroll
    for (int p = 0; p < 3; p++) {
        float lo0, hi0, lo1, hi1, lo2, hi2, lo3, hi3;
        unpack2(acc[p][0], lo0, hi0);
        unpack2(acc[p][1], lo1, hi1);
        unpack2(acc[p][2], lo2, hi2);
        unpack2(acc[p][3], lo3, hi3);
        int rg = r0 + wrp * ROWS_W + 2 * p;
        if (rg < N_DST) {
            float4 res;
            res.x = fmaxf(lo0 + bv.x, 0.0f);
            res.y = fmaxf(lo1 + bv.y, 0.0f);
            res.z = fmaxf(lo2 + bv.z, 0.0f);
            res.w = fmaxf(lo3 + bv.w, 0.0f);
            *(float4*)&out[rg * OUT_F + lane * 4] = res;
        }
        if (rg + 1 < N_DST) {
            float4 res;
            res.x = fmaxf(hi0 + bv.x, 0.0f);
            res.y = fmaxf(hi1 + bv.y, 0.0f);
            res.z = fmaxf(hi2 + bv.z, 0.0f);
            res.w = fmaxf(hi3 + bv.w, 0.0f);
            *(float4*)&out[(rg + 1) * OUT_F + lane * 4] = res;
        }
    }
}

// ---------------------------------------------------------------------------
extern "C" void kernel_launch(void* const* d_in, const int* in_sizes, int n_in,
                              void* d_out, int out_size) {
    const float* h    = (const float*)d_in[0];
    const int*   esrc = (const int*)d_in[1];    // int32: JAX x64 disabled
    const int*   edst = (const int*)d_in[2];    // int32
    const float* W    = (const float*)d_in[3];
    const float* bias = (const float*)d_in[4];
    float*       out  = (float*)d_out;

    cudaFuncSetAttribute(gemm_kernel,
                         cudaFuncAttributeMaxDynamicSharedMemorySize, SMEM_BYTES);

    void* count_ptr = nullptr;
    cudaGetSymbolAddress(&count_ptr, g_count);
    cudaMemsetAsync(count_ptr, 0, N_DST * sizeof(int));

    wt_kernel<<<(OUT_F * KDIM + 255) / 256, 256>>>(W);
    count_kernel<<<(NE / 4 + 255) / 256, 256>>>((const int4*)edst);
    scan_kernel<<<1, 1024>>>();
    fill_kernel<<<(NE / 4 + 255) / 256, 256>>>((const int4*)esrc, (const int4*)edst);
    agg_kernel<<<(N_DST * 32 + 255) / 256, 256>>>((const float4*)h);
    gemm_kernel<<<(N_DST + BM - 1) / BM, 256, SMEM_BYTES>>>(h, bias, out);
}